// round 15
// baseline (speedup 1.0000x reference)
#include <cuda_runtime.h>
#include <cuda_fp16.h>
#include <cstdint>

#define NBLK    128
#define THREADS 288
#define NCW     256            // compute threads (warps 0-7)
#define STAGES  5
#define A_BYTES 10240          // 2 K32 A-blocks of 64 rows x 40 halves
#define B_BYTES 20480          // 2 K32 B-blocks of 128 rows x 40 halves
#define STAGE_BYTES 30720

// ---------------- device globals: fp16 pre-packed tile images (stride 40) ---
__device__ __half g_xA[256 * 4 * 2 * 2560];     // [t][mt][kc] A-blocks
__device__ __half g_hA0[2 * 4 * 16 * 2560];     // [par][mt][strip]
__device__ __half g_hA1[2 * 4 * 16 * 2560];
__device__ __half g_Bp0[16 * 18 * 5120];        // [strip][kt32] B-blocks
__device__ __half g_Bp1[16 * 32 * 5120];
__device__ float g_bias0[16 * 128];
__device__ float g_bias1[16 * 128];
__device__ float g_part[64 * 8192];             // per-tile fp32 gate partials
__device__ unsigned g_pflag[64];
__device__ float g_h1x[256 * 512];
__device__ __align__(128) unsigned g_done[4 * 32];   // flag-array barrier (128B/group)

// ---------------- helpers ----------------------------------------------------
__device__ __forceinline__ uint32_t smem_u32(const void* p) {
    uint32_t a;
    asm("{ .reg .u64 t; cvta.to.shared.u64 t, %1; cvt.u32.u64 %0, t; }" : "=r"(a) : "l"(p));
    return a;
}
__device__ __forceinline__ unsigned ld_acq(const unsigned* p) {
    unsigned v;
    asm volatile("ld.acquire.gpu.global.b32 %0, [%1];" : "=r"(v) : "l"(p) : "memory");
    return v;
}
__device__ __forceinline__ unsigned ld_rlx(const unsigned* p) {
    unsigned v;
    asm volatile("ld.relaxed.gpu.global.b32 %0, [%1];" : "=r"(v) : "l"(p) : "memory");
    return v;
}
__device__ __forceinline__ void st_rel(unsigned* p, unsigned v) {
    asm volatile("st.release.gpu.global.b32 [%0], %1;" :: "l"(p), "r"(v) : "memory");
}
#define BARC() asm volatile("bar.sync 1, 256;" ::: "memory")   // compute warps only
#define MBAR_INIT(a, n) \
    asm volatile("mbarrier.init.shared.b64 [%0], %1;" :: "r"(a), "r"((uint32_t)(n)) : "memory")
#define MBAR_EXPECT_TX(a, b) \
    asm volatile("mbarrier.arrive.expect_tx.shared.b64 _, [%0], %1;" :: "r"(a), "r"((uint32_t)(b)) : "memory")
#define MBAR_ARRIVE(a) \
    asm volatile("mbarrier.arrive.shared.b64 _, [%0];" :: "r"(a) : "memory")
#define MBAR_WAIT(a, p) do {                                                               \
    asm volatile("{\n\t.reg .pred P1;\n\t"                                                 \
        "WL_%=:\n\t"                                                                       \
        "mbarrier.try_wait.parity.acquire.cta.shared::cta.b64 P1, [%0], %1, 0x989680;\n\t" \
        "@P1 bra.uni WD_%=;\n\t"                                                           \
        "bra.uni WL_%=;\n\t"                                                               \
        "WD_%=:\n\t}"                                                                      \
        :: "r"(a), "r"((uint32_t)(p)) : "memory");                                         \
} while (0)
#define BULK_G2S(dst, src, bytes, mbar)                                                    \
    asm volatile("cp.async.bulk.shared::cluster.global.mbarrier::complete_tx::bytes "      \
                 "[%0], [%1], %2, [%3];"                                                   \
        :: "r"(dst), "l"(src), "r"((uint32_t)(bytes)), "r"(mbar) : "memory")

__device__ __forceinline__ void mma16(float* c, const uint32_t* a, uint32_t b0, uint32_t b1) {
    asm volatile(
        "mma.sync.aligned.m16n8k16.row.col.f32.f16.f16.f32 "
        "{%0,%1,%2,%3},{%4,%5,%6,%7},{%8,%9},{%0,%1,%2,%3};"
        : "+f"(c[0]), "+f"(c[1]), "+f"(c[2]), "+f"(c[3])
        : "r"(a[0]), "r"(a[1]), "r"(a[2]), "r"(a[3]), "r"(b0), "r"(b1));
}
__device__ __forceinline__ float hw_tanh(float x) {
    float y; asm("tanh.approx.f32 %0, %1;" : "=f"(y) : "f"(x));
    return y;
}
__device__ __forceinline__ float fsig(float x) { return fmaf(hw_tanh(0.5f * x), 0.5f, 0.5f); }
__device__ __forceinline__ uint32_t pk2(float a, float b) {
    __half2 h = __floats2half2_rn(a, b);
    return *(uint32_t*)&h;
}

// ---------------- prep kernels ------------------------------------------------
__global__ void prep_x(const float* __restrict__ x) {
    int idx = blockIdx.x * blockDim.x + threadIdx.x;
    if (idx >= 256 * 4 * 2 * 64 * 32) return;
    int kk = idx & 31;
    int r  = (idx >> 5) & 63;
    int kc = (idx >> 11) & 1;
    int mt = (idx >> 12) & 3;
    int t  = idx >> 14;
    int b = mt * 64 + r, d = kc * 32 + kk;
    g_xA[(size_t)((t * 4 + mt) * 2 + kc) * 2560 + r * 40 + kk] =
        __float2half(x[(b * 256 + t) * 64 + d]);
}
__global__ void prep_w(const float* __restrict__ Wih0, const float* __restrict__ Whh0,
                       const float* __restrict__ bih0, const float* __restrict__ bhh0,
                       const float* __restrict__ Wih1, const float* __restrict__ Whh1,
                       const float* __restrict__ bih1, const float* __restrict__ bhh1) {
    int idx = blockIdx.x * blockDim.x + threadIdx.x;
    const int NW0 = 16 * 18 * 128 * 32;
    const int NW1 = 16 * 32 * 128 * 32;
    if (idx < NW0) {
        int kk = idx & 31;
        int n  = (idx >> 5) & 127;
        int kt = (idx >> 12) % 18;
        int nt = idx / (18 * 4096);
        int row = (n & 3) * 512 + nt * 32 + (n >> 2);
        int k = kt * 32 + kk;
        float v = (k < 64) ? Wih0[row * 64 + k] : Whh0[row * 512 + (k - 64)];
        g_Bp0[(size_t)(nt * 18 + kt) * 5120 + n * 40 + kk] = __float2half(v);
    } else if (idx < NW0 + NW1) {
        int j = idx - NW0;
        int kk = j & 31;
        int n  = (j >> 5) & 127;
        int kt = (j >> 12) & 31;
        int nt = j >> 17;
        int row = (n & 3) * 512 + nt * 32 + (n >> 2);
        int k = kt * 32 + kk;
        float v = (k < 512) ? Wih1[row * 512 + k] : Whh1[row * 512 + (k - 512)];
        g_Bp1[(size_t)(nt * 32 + kt) * 5120 + n * 40 + kk] = __float2half(v);
    } else if (idx < NW0 + NW1 + 2 * 2048) {
        int j = idx - NW0 - NW1;
        int l = j >> 11;
        int rr = j & 2047;
        int c = rr & 127, nt = rr >> 7;
        int row = (c & 3) * 512 + nt * 32 + (c >> 2);
        float v = l ? (bih1[row] + bhh1[row]) : (bih0[row] + bhh0[row]);
        (l ? g_bias1 : g_bias0)[rr] = v;
    }
}
__global__ void prep_zero() {
    int idx = blockIdx.x * blockDim.x + threadIdx.x;
    if (idx < 2 * 4 * 16 * 2560) {
        g_hA0[idx] = __float2half(0.f);
        g_hA1[idx] = __float2half(0.f);
    }
    if (idx < 64) g_pflag[idx] = 0u;
    if (idx < 128) g_done[idx] = 0u;
}

// ---------------- persistent LSTM kernel ---------------------------------------
__global__ __launch_bounds__(THREADS, 1)
void lstm_persistent(const float* __restrict__ Wfc, const float* __restrict__ bfc,
                     float* __restrict__ out) {
    extern __shared__ char dsm_raw[];
    __shared__ __align__(8) unsigned long long mb_full[STAGES], mb_empty[STAGES];
    __shared__ float Gs[64 * 132];
    __shared__ float bias_s[128];
    __shared__ float red[NCW];

    const int tid   = threadIdx.x;
    const int lane  = tid & 31;
    const int warp  = tid >> 5;
    const int warpM = warp >> 2;   // 0..1 (compute warps only)
    const int warpN = warp & 3;
    const int bid   = blockIdx.x;
    const int layer = bid >> 6;
    const int tile  = bid & 63;
    const int mt    = tile & 3;
    const int strip = tile >> 2;
    const int gslot = layer * 16 + strip;     // 0..31 within mt group
    const bool is_comp = (tid < NCW);
    const bool is_prod = (tid == NCW);        // single producer thread

    uint32_t rawu  = smem_u32(dsm_raw);
    uint32_t dsm_u = (rawu + 127u) & ~127u;
    char* sbase = dsm_raw + (dsm_u - rawu);
    uint32_t fullA[STAGES], emptyA[STAGES], aSt[STAGES];
#pragma unroll
    for (int s = 0; s < STAGES; s++) {
        aSt[s] = dsm_u + s * STAGE_BYTES;
        fullA[s]  = smem_u32(&mb_full[s]);
        emptyA[s] = smem_u32(&mb_empty[s]);
    }
    if (tid == 0) {
#pragma unroll
        for (int s = 0; s < STAGES; s++) { MBAR_INIT(fullA[s], 1); MBAR_INIT(emptyA[s], 8); }
    }
    for (int i = tid; i < 128; i += THREADS)
        bias_s[i] = ((layer ? g_bias1 : g_bias0) + strip * 128)[i];
    __syncthreads();

    float cst[8];
#pragma unroll
    for (int j = 0; j < 8; j++) cst[j] = 0.f;
    float acc[2][4][4];

    int p_st = 0, p_ph = 1;   // producer cursor
    int c_st = 0, c_ph = 0;   // consumer cursor
    unsigned target = 0;

    for (int s = 0; s <= 256; s++) {
        const int rp = (s + 1) & 1;
        const int pidx = (layer == 0 && s >= 1) ? 4 : 0;
        int nch;
        if (layer == 0) nch = pidx + (s < 256 ? 9 : 0);
        else            nch = (s >= 1) ? 12 : 0;

        if (nch > 0) {
            if (is_prod) {
                // -------- producer: issue every chunk, throttled by empty stages
                for (int c = 0; c < nch; c++) {
                    const __half* a;
                    const __half* b;
                    if (layer == 0) {
                        if (c < pidx) {
                            a = g_hA1 + (size_t)((rp * 4 + mt) * 16 + 8 + 2 * c) * 2560;
                            b = g_Bp1 + (size_t)(strip * 32 + 24 + 2 * c) * 5120;
                        } else {
                            int j = c - pidx;
                            a = (j == 0) ? g_xA + (size_t)((s * 4 + mt) * 2) * 2560
                                         : g_hA0 + (size_t)((rp * 4 + mt) * 16 + (j - 1) * 2) * 2560;
                            b = g_Bp0 + (size_t)(strip * 18 + 2 * j) * 5120;
                        }
                    } else {
                        a = (c < 8) ? g_hA0 + (size_t)((rp * 4 + mt) * 16 + 2 * c) * 2560
                                    : g_hA1 + (size_t)((rp * 4 + mt) * 16 + (2 * c - 16)) * 2560;
                        b = g_Bp1 + (size_t)(strip * 32 + 2 * c) * 5120;
                    }
                    MBAR_WAIT(emptyA[p_st], p_ph);
                    MBAR_EXPECT_TX(fullA[p_st], STAGE_BYTES);
                    BULK_G2S(aSt[p_st], a, A_BYTES, fullA[p_st]);
                    BULK_G2S(aSt[p_st] + A_BYTES, b, B_BYTES, fullA[p_st]);
                    if (++p_st == STAGES) { p_st = 0; p_ph ^= 1; }
                }
            } else if (is_comp) {
                // -------- compute warps: r8/r12 core unchanged
#pragma unroll
                for (int mi = 0; mi < 2; mi++)
#pragma unroll
                    for (int ni = 0; ni < 4; ni++)
#pragma unroll
                        for (int q = 0; q < 4; q++) acc[mi][ni][q] = 0.f;

                for (int c = 0; c < nch; c++) {
                    int st = c_st;
                    MBAR_WAIT(fullA[st], c_ph);
                    if (++c_st == STAGES) { c_st = 0; c_ph ^= 1; }

                    const uint32_t* stW = (const uint32_t*)(sbase + st * STAGE_BYTES);
#pragma unroll
                    for (int sub = 0; sub < 2; sub++) {
                        const uint32_t* aw = stW + sub * 1280;
                        const uint32_t* bw = stW + 2560 + sub * 2560;
#pragma unroll
                        for (int kk = 0; kk < 2; kk++) {
                            uint32_t af[2][4], bf[4][2];
#pragma unroll
                            for (int mi = 0; mi < 2; mi++) {
                                int rb = warpM * 32 + mi * 16 + (lane >> 2);
                                int wi = rb * 20 + (lane & 3) + kk * 8;
                                af[mi][0] = aw[wi];
                                af[mi][1] = aw[wi + 160];
                                af[mi][2] = aw[wi + 4];
                                af[mi][3] = aw[wi + 164];
                            }
#pragma unroll
                            for (int ni = 0; ni < 4; ni++) {
                                int nb = warpN * 32 + ni * 8 + (lane >> 2);
                                int wi = nb * 20 + (lane & 3) + kk * 8;
                                bf[ni][0] = bw[wi];
                                bf[ni][1] = bw[wi + 4];
                            }
#pragma unroll
                            for (int mi = 0; mi < 2; mi++)
#pragma unroll
                                for (int ni = 0; ni < 4; ni++)
                                    mma16(acc[mi][ni], af[mi], bf[ni][0], bf[ni][1]);
                        }
                    }
                    if (lane == 0) MBAR_ARRIVE(emptyA[st]);

                    if (layer == 0 && pidx && c == pidx - 1) {
                        float2* pp = (float2*)&g_part[(size_t)tile * 8192];
#pragma unroll
                        for (int mi = 0; mi < 2; mi++) {
                            int rr = warpM * 32 + mi * 16 + (lane >> 2);
#pragma unroll
                            for (int ni = 0; ni < 4; ni++) {
                                int cc = warpN * 32 + ni * 8 + (lane & 3) * 2;
                                pp[(rr * 128 + cc) >> 1]       = make_float2(acc[mi][ni][0], acc[mi][ni][1]);
                                pp[((rr + 8) * 128 + cc) >> 1] = make_float2(acc[mi][ni][2], acc[mi][ni][3]);
                            }
                        }
                        BARC();
                        if (tid == 0) st_rel(&g_pflag[tile], (unsigned)s);
#pragma unroll
                        for (int mi = 0; mi < 2; mi++)
#pragma unroll
                            for (int ni = 0; ni < 4; ni++)
#pragma unroll
                                for (int q = 0; q < 4; q++) acc[mi][ni][q] = 0.f;
                    }
                }

                // -------- epilogue (compute warps only)
                bool do_epi = (layer == 1) || (s < 256);
                if (do_epi) {
#pragma unroll
                    for (int mi = 0; mi < 2; mi++) {
                        int rr = warpM * 32 + mi * 16 + (lane >> 2);
#pragma unroll
                        for (int ni = 0; ni < 4; ni++) {
                            int cc = warpN * 32 + ni * 8 + (lane & 3) * 2;
                            Gs[rr * 132 + cc]           = acc[mi][ni][0];
                            Gs[rr * 132 + cc + 1]       = acc[mi][ni][1];
                            Gs[(rr + 8) * 132 + cc]     = acc[mi][ni][2];
                            Gs[(rr + 8) * 132 + cc + 1] = acc[mi][ni][3];
                        }
                    }
                    BARC();

                    int r   = tid >> 2;
                    int hl0 = (tid & 3) * 8;
                    float hv[8];
                    if (layer == 0) {
#pragma unroll
                        for (int j = 0; j < 8; j++) {
                            int c4 = (hl0 + j) * 4;
                            float ip = Gs[r * 132 + c4 + 0] + bias_s[c4 + 0];
                            float fp = Gs[r * 132 + c4 + 1] + bias_s[c4 + 1];
                            float gp = Gs[r * 132 + c4 + 2] + bias_s[c4 + 2];
                            float op = Gs[r * 132 + c4 + 3] + bias_s[c4 + 3];
                            float cn = fsig(fp) * cst[j] + fsig(ip) * hw_tanh(gp);
                            cst[j] = cn;
                            hv[j] = fsig(op) * hw_tanh(cn);
                        }
                        __half* hout = g_hA0 + (size_t)(((s & 1) * 4 + mt) * 16 + strip) * 2560;
                        uint4 v = { pk2(hv[0], hv[1]), pk2(hv[2], hv[3]),
                                    pk2(hv[4], hv[5]), pk2(hv[6], hv[7]) };
                        *(uint4*)(&hout[r * 40 + hl0]) = v;
                    } else {
                        while (ld_acq(&g_pflag[tile]) < (unsigned)s) { }
                        const float4* pin =
                            (const float4*)&g_part[(size_t)tile * 8192 + r * 128 + (tid & 3) * 32];
#pragma unroll
                        for (int j = 0; j < 8; j++) {
                            int c4 = (hl0 + j) * 4;
                            float4 pv = __ldcg(&pin[j]);
                            float ip = Gs[r * 132 + c4 + 0] + bias_s[c4 + 0] + pv.x;
                            float fp = Gs[r * 132 + c4 + 1] + bias_s[c4 + 1] + pv.y;
                            float gp = Gs[r * 132 + c4 + 2] + bias_s[c4 + 2] + pv.z;
                            float op = Gs[r * 132 + c4 + 3] + bias_s[c4 + 3] + pv.w;
                            float cn = fsig(fp) * cst[j] + fsig(ip) * hw_tanh(gp);
                            cst[j] = cn;
                            hv[j] = fsig(op) * hw_tanh(cn);
                        }
                        __half* hout = g_hA1 + (size_t)(((s & 1) * 4 + mt) * 16 + strip) * 2560;
                        uint4 v = { pk2(hv[0], hv[1]), pk2(hv[2], hv[3]),
                                    pk2(hv[4], hv[5]), pk2(hv[6], hv[7]) };
                        *(uint4*)(&hout[r * 40 + hl0]) = v;
                        if (s == 256) {
#pragma unroll
                            for (int j = 0; j < 8; j++)
                                g_h1x[(mt * 64 + r) * 512 + strip * 32 + hl0 + j] = hv[j];
                        }
                    }
                }
            }
        }

        // -------- per-mt group barrier: parallel flags, morally-strong polls ----
        target++;
        __syncthreads();
        if (tid == 0) {
            __threadfence();
            st_rel(&g_done[(mt << 5) + gslot], target);
        }
        if (warp == 0) {
            while (ld_rlx(&g_done[(mt << 5) + lane]) < target) { }
            asm volatile("fence.acq_rel.gpu;" ::: "memory");
        }
        __syncthreads();
    }

    // -------- final FC (compute warps only) --------
    if (is_comp) {
        int gidx = layer ? (16 + strip) : strip;
        for (int r2 = 0; r2 < 2; r2++) {
            int b = mt * 64 + 2 * gidx + r2;
            float p = 0.f;
            for (int k = tid; k < 512; k += NCW)
                p += __ldcg(&g_h1x[b * 512 + k]) * __ldg(&Wfc[k]);
            red[tid] = p;
            BARC();
            for (int off = 128; off > 0; off >>= 1) {
                if (tid < off) red[tid] += red[tid + off];
                BARC();
            }
            if (tid == 0) out[b] = red[0] + __ldg(bfc);
            BARC();
        }
    }
}

// ---------------- launch --------------------------------------------------------
extern "C" void kernel_launch(void* const* d_in, const int* in_sizes, int n_in,
                              void* d_out, int out_size) {
    const float* x    = (const float*)d_in[0];
    const float* Wih0 = (const float*)d_in[1];
    const float* Whh0 = (const float*)d_in[2];
    const float* bih0 = (const float*)d_in[3];
    const float* bhh0 = (const float*)d_in[4];
    const float* Wih1 = (const float*)d_in[5];
    const float* Whh1 = (const float*)d_in[6];
    const float* bih1 = (const float*)d_in[7];
    const float* bhh1 = (const float*)d_in[8];
    const float* Wfc  = (const float*)d_in[9];
    const float* bfc  = (const float*)d_in[10];
    float* out = (float*)d_out;

    cudaFuncSetAttribute(lstm_persistent,
                         cudaFuncAttributeMaxDynamicSharedMemorySize,
                         STAGES * STAGE_BYTES + 256);

    prep_x<<<(256 * 4 * 2 * 64 * 32 + 255) / 256, 256>>>(x);
    int wtot = 16 * 18 * 128 * 32 + 16 * 32 * 128 * 32 + 2 * 2048;
    prep_w<<<(wtot + 255) / 256, 256>>>(Wih0, Whh0, bih0, bhh0, Wih1, Whh1, bih1, bhh1);
    prep_zero<<<(2 * 4 * 16 * 2560 + 255) / 256, 256>>>();
    lstm_persistent<<<NBLK, THREADS, STAGES * STAGE_BYTES + 256>>>(Wfc, bfc, out);
}

// round 16
// speedup vs baseline: 1.1901x; 1.1901x over previous
#include <cuda_runtime.h>
#include <cuda_fp16.h>
#include <cstdint>

#define NBLK    128
#define THREADS 288
#define NCW     256            // compute threads (warps 0-7)
#define STAGES  5
#define A_BYTES 10240          // 2 K32 A-blocks of 64 rows x 40 halves
#define B_BYTES 20480          // 2 K32 B-blocks of 128 rows x 40 halves
#define STAGE_BYTES 30720
#define PF_BYTES 32768         // 64 x 128 fp32 partial tile
#define DYN_BYTES (STAGES * STAGE_BYTES + PF_BYTES)   // 186368

// ---------------- device globals: fp16 pre-packed tile images (stride 40) ---
__device__ __half g_xA[256 * 4 * 2 * 2560];     // [t][mt][kc] A-blocks
__device__ __half g_hA0[2 * 4 * 16 * 2560];     // [par][mt][strip]
__device__ __half g_hA1[2 * 4 * 16 * 2560];
__device__ __half g_Bp0[16 * 18 * 5120];        // [strip][kt32] B-blocks
__device__ __half g_Bp1[16 * 32 * 5120];
__device__ float g_bias0[16 * 128];
__device__ float g_bias1[16 * 128];
__device__ float g_part[64 * 8192];             // per-tile fp32 gate partials
__device__ unsigned g_pflag[64];
__device__ float g_h1x[256 * 512];
__device__ unsigned g_cnt[4 * 32];              // per-mt group barrier
__device__ unsigned g_phs[4 * 32];

// ---------------- helpers ----------------------------------------------------
__device__ __forceinline__ uint32_t smem_u32(const void* p) {
    uint32_t a;
    asm("{ .reg .u64 t; cvta.to.shared.u64 t, %1; cvt.u32.u64 %0, t; }" : "=r"(a) : "l"(p));
    return a;
}
__device__ __forceinline__ unsigned ld_acq(const unsigned* p) {
    unsigned v;
    asm volatile("ld.acquire.gpu.global.b32 %0, [%1];" : "=r"(v) : "l"(p) : "memory");
    return v;
}
__device__ __forceinline__ unsigned atom_add_acqrel(unsigned* p, unsigned v) {
    unsigned o;
    asm volatile("atom.add.acq_rel.gpu.global.u32 %0, [%1], %2;" : "=r"(o) : "l"(p), "r"(v) : "memory");
    return o;
}
__device__ __forceinline__ void st_rel(unsigned* p, unsigned v) {
    asm volatile("st.release.gpu.global.b32 [%0], %1;" :: "l"(p), "r"(v) : "memory");
}
#define BARC() asm volatile("bar.sync 1, 256;" ::: "memory")   // compute warps only
#define MBAR_INIT(a, n) \
    asm volatile("mbarrier.init.shared.b64 [%0], %1;" :: "r"(a), "r"((uint32_t)(n)) : "memory")
#define MBAR_EXPECT_TX(a, b) \
    asm volatile("mbarrier.arrive.expect_tx.shared.b64 _, [%0], %1;" :: "r"(a), "r"((uint32_t)(b)) : "memory")
#define MBAR_ARRIVE(a) \
    asm volatile("mbarrier.arrive.shared.b64 _, [%0];" :: "r"(a) : "memory")
#define MBAR_WAIT(a, p) do {                                                               \
    asm volatile("{\n\t.reg .pred P1;\n\t"                                                 \
        "WL_%=:\n\t"                                                                       \
        "mbarrier.try_wait.parity.acquire.cta.shared::cta.b64 P1, [%0], %1, 0x989680;\n\t" \
        "@P1 bra.uni WD_%=;\n\t"                                                           \
        "bra.uni WL_%=;\n\t"                                                               \
        "WD_%=:\n\t}"                                                                      \
        :: "r"(a), "r"((uint32_t)(p)) : "memory");                                         \
} while (0)
#define BULK_G2S(dst, src, bytes, mbar)                                                    \
    asm volatile("cp.async.bulk.shared::cluster.global.mbarrier::complete_tx::bytes "      \
                 "[%0], [%1], %2, [%3];"                                                   \
        :: "r"(dst), "l"(src), "r"((uint32_t)(bytes)), "r"(mbar) : "memory")

__device__ __forceinline__ void mma16(float* c, const uint32_t* a, uint32_t b0, uint32_t b1) {
    asm volatile(
        "mma.sync.aligned.m16n8k16.row.col.f32.f16.f16.f32 "
        "{%0,%1,%2,%3},{%4,%5,%6,%7},{%8,%9},{%0,%1,%2,%3};"
        : "+f"(c[0]), "+f"(c[1]), "+f"(c[2]), "+f"(c[3])
        : "r"(a[0]), "r"(a[1]), "r"(a[2]), "r"(a[3]), "r"(b0), "r"(b1));
}
__device__ __forceinline__ float hw_tanh(float x) {
    float y; asm("tanh.approx.f32 %0, %1;" : "=f"(y) : "f"(x));
    return y;
}
__device__ __forceinline__ float fsig(float x) { return fmaf(hw_tanh(0.5f * x), 0.5f, 0.5f); }
__device__ __forceinline__ uint32_t pk2(float a, float b) {
    __half2 h = __floats2half2_rn(a, b);
    return *(uint32_t*)&h;
}

// ---------------- prep kernels ------------------------------------------------
__global__ void prep_x(const float* __restrict__ x) {
    int idx = blockIdx.x * blockDim.x + threadIdx.x;
    if (idx >= 256 * 4 * 2 * 64 * 32) return;
    int kk = idx & 31;
    int r  = (idx >> 5) & 63;
    int kc = (idx >> 11) & 1;
    int mt = (idx >> 12) & 3;
    int t  = idx >> 14;
    int b = mt * 64 + r, d = kc * 32 + kk;
    g_xA[(size_t)((t * 4 + mt) * 2 + kc) * 2560 + r * 40 + kk] =
        __float2half(x[(b * 256 + t) * 64 + d]);
}
__global__ void prep_w(const float* __restrict__ Wih0, const float* __restrict__ Whh0,
                       const float* __restrict__ bih0, const float* __restrict__ bhh0,
                       const float* __restrict__ Wih1, const float* __restrict__ Whh1,
                       const float* __restrict__ bih1, const float* __restrict__ bhh1) {
    int idx = blockIdx.x * blockDim.x + threadIdx.x;
    const int NW0 = 16 * 18 * 128 * 32;
    const int NW1 = 16 * 32 * 128 * 32;
    if (idx < NW0) {
        int kk = idx & 31;
        int n  = (idx >> 5) & 127;
        int kt = (idx >> 12) % 18;
        int nt = idx / (18 * 4096);
        int row = (n & 3) * 512 + nt * 32 + (n >> 2);
        int k = kt * 32 + kk;
        float v = (k < 64) ? Wih0[row * 64 + k] : Whh0[row * 512 + (k - 64)];
        g_Bp0[(size_t)(nt * 18 + kt) * 5120 + n * 40 + kk] = __float2half(v);
    } else if (idx < NW0 + NW1) {
        int j = idx - NW0;
        int kk = j & 31;
        int n  = (j >> 5) & 127;
        int kt = (j >> 12) & 31;
        int nt = j >> 17;
        int row = (n & 3) * 512 + nt * 32 + (n >> 2);
        int k = kt * 32 + kk;
        float v = (k < 512) ? Wih1[row * 512 + k] : Whh1[row * 512 + (k - 512)];
        g_Bp1[(size_t)(nt * 32 + kt) * 5120 + n * 40 + kk] = __float2half(v);
    } else if (idx < NW0 + NW1 + 2 * 2048) {
        int j = idx - NW0 - NW1;
        int l = j >> 11;
        int rr = j & 2047;
        int c = rr & 127, nt = rr >> 7;
        int row = (c & 3) * 512 + nt * 32 + (c >> 2);
        float v = l ? (bih1[row] + bhh1[row]) : (bih0[row] + bhh0[row]);
        (l ? g_bias1 : g_bias0)[rr] = v;
    }
}
__global__ void prep_zero() {
    int idx = blockIdx.x * blockDim.x + threadIdx.x;
    if (idx < 2 * 4 * 16 * 2560) {
        g_hA0[idx] = __float2half(0.f);
        g_hA1[idx] = __float2half(0.f);
    }
    if (idx < 64) g_pflag[idx] = 0u;
    if (idx < 128) { g_cnt[idx] = 0u; g_phs[idx] = 0u; }
}

// ---------------- persistent LSTM kernel ---------------------------------------
__global__ __launch_bounds__(THREADS, 1)
void lstm_persistent(const float* __restrict__ Wfc, const float* __restrict__ bfc,
                     float* __restrict__ out) {
    extern __shared__ char dsm_raw[];
    __shared__ __align__(8) unsigned long long mb_full[STAGES], mb_empty[STAGES];
    __shared__ __align__(8) unsigned long long mb_pf, mb_pe;
    __shared__ float Gs[64 * 132];
    __shared__ float bias_s[128];
    __shared__ float red[NCW];

    const int tid   = threadIdx.x;
    const int lane  = tid & 31;
    const int warp  = tid >> 5;
    const int warpM = warp >> 2;   // 0..1 (compute warps only)
    const int warpN = warp & 3;
    const int bid   = blockIdx.x;
    const int layer = bid >> 6;
    const int tile  = bid & 63;
    const int mt    = tile & 3;
    const int strip = tile >> 2;
    const bool is_comp = (tid < NCW);
    const bool is_prod = (tid == NCW);   // single producer thread (warp 8 lane 0)

    uint32_t rawu  = smem_u32(dsm_raw);
    uint32_t dsm_u = (rawu + 127u) & ~127u;
    char* sbase = dsm_raw + (dsm_u - rawu);
    uint32_t fullA[STAGES], emptyA[STAGES], aSt[STAGES];
#pragma unroll
    for (int s = 0; s < STAGES; s++) {
        aSt[s] = dsm_u + s * STAGE_BYTES;
        fullA[s]  = smem_u32(&mb_full[s]);
        emptyA[s] = smem_u32(&mb_empty[s]);
    }
    const uint32_t pfS = dsm_u + STAGES * STAGE_BYTES;     // partial smem buffer
    const uint32_t pfA = smem_u32(&mb_pf);
    const uint32_t peA = smem_u32(&mb_pe);
    char* pf_base = sbase + STAGES * STAGE_BYTES;

    if (tid == 0) {
#pragma unroll
        for (int s = 0; s < STAGES; s++) { MBAR_INIT(fullA[s], 1); MBAR_INIT(emptyA[s], 8); }
        MBAR_INIT(pfA, 1); MBAR_INIT(peA, 8);
    }
    for (int i = tid; i < 128; i += THREADS)
        bias_s[i] = ((layer ? g_bias1 : g_bias0) + strip * 128)[i];
    __syncthreads();

    float cst[8];
#pragma unroll
    for (int j = 0; j < 8; j++) cst[j] = 0.f;
    float acc[2][4][4];

    int p_st = 0, p_ph = 1;   // producer stage cursor
    int c_st = 0, c_ph = 0;   // consumer stage cursor
    int pe_ph = 1, pf_ph = 0; // partial-buffer cursors
    unsigned target = 0;

    for (int s = 0; s <= 256; s++) {
        const int rp = (s + 1) & 1;
        const int pidx = (layer == 0 && s >= 1) ? 4 : 0;
        int nch;
        if (layer == 0) nch = pidx + (s < 256 ? 9 : 0);
        else            nch = (s >= 1) ? 12 : 0;

        if (nch > 0) {
            if (is_prod) {
                // -------- producer: issue chunks, then prefetch L1 partials to smem
                for (int c = 0; c < nch; c++) {
                    const __half* a;
                    const __half* b;
                    if (layer == 0) {
                        if (c < pidx) {
                            a = g_hA1 + (size_t)((rp * 4 + mt) * 16 + 8 + 2 * c) * 2560;
                            b = g_Bp1 + (size_t)(strip * 32 + 24 + 2 * c) * 5120;
                        } else {
                            int j = c - pidx;
                            a = (j == 0) ? g_xA + (size_t)((s * 4 + mt) * 2) * 2560
                                         : g_hA0 + (size_t)((rp * 4 + mt) * 16 + (j - 1) * 2) * 2560;
                            b = g_Bp0 + (size_t)(strip * 18 + 2 * j) * 5120;
                        }
                    } else {
                        a = (c < 8) ? g_hA0 + (size_t)((rp * 4 + mt) * 16 + 2 * c) * 2560
                                    : g_hA1 + (size_t)((rp * 4 + mt) * 16 + (2 * c - 16)) * 2560;
                        b = g_Bp1 + (size_t)(strip * 32 + 2 * c) * 5120;
                    }
                    MBAR_WAIT(emptyA[p_st], p_ph);
                    MBAR_EXPECT_TX(fullA[p_st], STAGE_BYTES);
                    BULK_G2S(aSt[p_st], a, A_BYTES, fullA[p_st]);
                    BULK_G2S(aSt[p_st] + A_BYTES, b, B_BYTES, fullA[p_st]);
                    if (++p_st == STAGES) { p_st = 0; p_ph ^= 1; }
                }
                if (layer == 1) {
                    while (ld_acq(&g_pflag[tile]) < (unsigned)s) { }
                    asm volatile("fence.proxy.async;" ::: "memory");
                    MBAR_WAIT(peA, pe_ph);
                    pe_ph ^= 1;
                    MBAR_EXPECT_TX(pfA, PF_BYTES);
                    BULK_G2S(pfS, (const void*)&g_part[(size_t)tile * 8192], PF_BYTES, pfA);
                }
            } else if (is_comp) {
                // -------- compute warps: r12 core unchanged
#pragma unroll
                for (int mi = 0; mi < 2; mi++)
#pragma unroll
                    for (int ni = 0; ni < 4; ni++)
#pragma unroll
                        for (int q = 0; q < 4; q++) acc[mi][ni][q] = 0.f;

                for (int c = 0; c < nch; c++) {
                    int st = c_st;
                    MBAR_WAIT(fullA[st], c_ph);
                    if (++c_st == STAGES) { c_st = 0; c_ph ^= 1; }

                    const uint32_t* stW = (const uint32_t*)(sbase + st * STAGE_BYTES);
#pragma unroll
                    for (int sub = 0; sub < 2; sub++) {
                        const uint32_t* aw = stW + sub * 1280;
                        const uint32_t* bw = stW + 2560 + sub * 2560;
#pragma unroll
                        for (int kk = 0; kk < 2; kk++) {
                            uint32_t af[2][4], bf[4][2];
#pragma unroll
                            for (int mi = 0; mi < 2; mi++) {
                                int rb = warpM * 32 + mi * 16 + (lane >> 2);
                                int wi = rb * 20 + (lane & 3) + kk * 8;
                                af[mi][0] = aw[wi];
                                af[mi][1] = aw[wi + 160];
                                af[mi][2] = aw[wi + 4];
                                af[mi][3] = aw[wi + 164];
                            }
#pragma unroll
                            for (int ni = 0; ni < 4; ni++) {
                                int nb = warpN * 32 + ni * 8 + (lane >> 2);
                                int wi = nb * 20 + (lane & 3) + kk * 8;
                                bf[ni][0] = bw[wi];
                                bf[ni][1] = bw[wi + 4];
                            }
#pragma unroll
                            for (int mi = 0; mi < 2; mi++)
#pragma unroll
                                for (int ni = 0; ni < 4; ni++)
                                    mma16(acc[mi][ni], af[mi], bf[ni][0], bf[ni][1]);
                        }
                    }
                    if (lane == 0) MBAR_ARRIVE(emptyA[st]);

                    if (layer == 0 && pidx && c == pidx - 1) {
                        float2* pp = (float2*)&g_part[(size_t)tile * 8192];
#pragma unroll
                        for (int mi = 0; mi < 2; mi++) {
                            int rr = warpM * 32 + mi * 16 + (lane >> 2);
#pragma unroll
                            for (int ni = 0; ni < 4; ni++) {
                                int cc = warpN * 32 + ni * 8 + (lane & 3) * 2;
                                pp[(rr * 128 + cc) >> 1]       = make_float2(acc[mi][ni][0], acc[mi][ni][1]);
                                pp[((rr + 8) * 128 + cc) >> 1] = make_float2(acc[mi][ni][2], acc[mi][ni][3]);
                            }
                        }
                        BARC();
                        if (tid == 0) st_rel(&g_pflag[tile], (unsigned)s);
#pragma unroll
                        for (int mi = 0; mi < 2; mi++)
#pragma unroll
                            for (int ni = 0; ni < 4; ni++)
#pragma unroll
                                for (int q = 0; q < 4; q++) acc[mi][ni][q] = 0.f;
                    }
                }

                // -------- epilogue (compute warps only)
                bool do_epi = (layer == 1) || (s < 256);
                if (do_epi) {
#pragma unroll
                    for (int mi = 0; mi < 2; mi++) {
                        int rr = warpM * 32 + mi * 16 + (lane >> 2);
#pragma unroll
                        for (int ni = 0; ni < 4; ni++) {
                            int cc = warpN * 32 + ni * 8 + (lane & 3) * 2;
                            Gs[rr * 132 + cc]           = acc[mi][ni][0];
                            Gs[rr * 132 + cc + 1]       = acc[mi][ni][1];
                            Gs[(rr + 8) * 132 + cc]     = acc[mi][ni][2];
                            Gs[(rr + 8) * 132 + cc + 1] = acc[mi][ni][3];
                        }
                    }
                    BARC();

                    int r   = tid >> 2;
                    int hl0 = (tid & 3) * 8;
                    float hv[8];
                    if (layer == 0) {
#pragma unroll
                        for (int j = 0; j < 8; j++) {
                            int c4 = (hl0 + j) * 4;
                            float ip = Gs[r * 132 + c4 + 0] + bias_s[c4 + 0];
                            float fp = Gs[r * 132 + c4 + 1] + bias_s[c4 + 1];
                            float gp = Gs[r * 132 + c4 + 2] + bias_s[c4 + 2];
                            float op = Gs[r * 132 + c4 + 3] + bias_s[c4 + 3];
                            float cn = fsig(fp) * cst[j] + fsig(ip) * hw_tanh(gp);
                            cst[j] = cn;
                            hv[j] = fsig(op) * hw_tanh(cn);
                        }
                        __half* hout = g_hA0 + (size_t)(((s & 1) * 4 + mt) * 16 + strip) * 2560;
                        uint4 v = { pk2(hv[0], hv[1]), pk2(hv[2], hv[3]),
                                    pk2(hv[4], hv[5]), pk2(hv[6], hv[7]) };
                        *(uint4*)(&hout[r * 40 + hl0]) = v;
                    } else {
                        MBAR_WAIT(pfA, pf_ph);
                        pf_ph ^= 1;
                        const float4* pin =
                            (const float4*)(pf_base + r * 512 + (tid & 3) * 128);
#pragma unroll
                        for (int j = 0; j < 8; j++) {
                            int c4 = (hl0 + j) * 4;
                            float4 pv = pin[j];
                            float ip = Gs[r * 132 + c4 + 0] + bias_s[c4 + 0] + pv.x;
                            float fp = Gs[r * 132 + c4 + 1] + bias_s[c4 + 1] + pv.y;
                            float gp = Gs[r * 132 + c4 + 2] + bias_s[c4 + 2] + pv.z;
                            float op = Gs[r * 132 + c4 + 3] + bias_s[c4 + 3] + pv.w;
                            float cn = fsig(fp) * cst[j] + fsig(ip) * hw_tanh(gp);
                            cst[j] = cn;
                            hv[j] = fsig(op) * hw_tanh(cn);
                        }
                        if (lane == 0) MBAR_ARRIVE(peA);
                        __half* hout = g_hA1 + (size_t)(((s & 1) * 4 + mt) * 16 + strip) * 2560;
                        uint4 v = { pk2(hv[0], hv[1]), pk2(hv[2], hv[3]),
                                    pk2(hv[4], hv[5]), pk2(hv[6], hv[7]) };
                        *(uint4*)(&hout[r * 40 + hl0]) = v;
                        if (s == 256) {
#pragma unroll
                            for (int j = 0; j < 8; j++)
                                g_h1x[(mt * 64 + r) * 512 + strip * 32 + hl0 + j] = hv[j];
                        }
                    }
                }
            }
        }

        // -------- per-mt group barrier (32 CTAs; all 288 threads sync) --------
        target++;
        __syncthreads();
        if (tid == 0) {
            __threadfence();
            unsigned a = atom_add_acqrel(&g_cnt[mt << 5], 1u) + 1u;
            if (a == target * 32u) st_rel(&g_phs[mt << 5], target);
            else while (ld_acq(&g_phs[mt << 5]) < target) { }
        }
        __syncthreads();
    }

    // -------- final FC (compute warps only) --------
    if (is_comp) {
        int gidx = layer ? (16 + strip) : strip;
        for (int r2 = 0; r2 < 2; r2++) {
            int b = mt * 64 + 2 * gidx + r2;
            float p = 0.f;
            for (int k = tid; k < 512; k += NCW)
                p += __ldcg(&g_h1x[b * 512 + k]) * __ldg(&Wfc[k]);
            red[tid] = p;
            BARC();
            for (int off = 128; off > 0; off >>= 1) {
                if (tid < off) red[tid] += red[tid + off];
                BARC();
            }
            if (tid == 0) out[b] = red[0] + __ldg(bfc);
            BARC();
        }
    }
}

// ---------------- launch --------------------------------------------------------
extern "C" void kernel_launch(void* const* d_in, const int* in_sizes, int n_in,
                              void* d_out, int out_size) {
    const float* x    = (const float*)d_in[0];
    const float* Wih0 = (const float*)d_in[1];
    const float* Whh0 = (const float*)d_in[2];
    const float* bih0 = (const float*)d_in[3];
    const float* bhh0 = (const float*)d_in[4];
    const float* Wih1 = (const float*)d_in[5];
    const float* Whh1 = (const float*)d_in[6];
    const float* bih1 = (const float*)d_in[7];
    const float* bhh1 = (const float*)d_in[8];
    const float* Wfc  = (const float*)d_in[9];
    const float* bfc  = (const float*)d_in[10];
    float* out = (float*)d_out;

    cudaFuncSetAttribute(lstm_persistent,
                         cudaFuncAttributeMaxDynamicSharedMemorySize,
                         DYN_BYTES + 256);

    prep_x<<<(256 * 4 * 2 * 64 * 32 + 255) / 256, 256>>>(x);
    int wtot = 16 * 18 * 128 * 32 + 16 * 32 * 128 * 32 + 2 * 2048;
    prep_w<<<(wtot + 255) / 256, 256>>>(Wih0, Whh0, bih0, bhh0, Wih1, Whh1, bih1, bhh1);
    prep_zero<<<(2 * 4 * 16 * 2560 + 255) / 256, 256>>>();
    lstm_persistent<<<NBLK, THREADS, DYN_BYTES + 256>>>(Wfc, bfc, out);
}

// round 17
// speedup vs baseline: 1.2275x; 1.0314x over previous
#include <cuda_runtime.h>
#include <cuda_fp16.h>
#include <cstdint>

#define NBLK    128
#define THREADS 288
#define NCW     256            // compute threads (warps 0-7)
#define STAGES  3
#define A_MAX   20480          // up to 4 K32 A-blocks (64 rows x 40 halves each)
#define B_MAX   40960          // up to 4 K32 B-blocks (128 rows x 40 halves each)
#define STAGE_BYTES (A_MAX + B_MAX)   // 61440

// ---------------- device globals: fp16 pre-packed tile images (stride 40) ---
__device__ __half g_xA[256 * 4 * 2 * 2560];     // [t][mt][kc] A-blocks
__device__ __half g_hA0[2 * 4 * 16 * 2560];     // [par][mt][strip]
__device__ __half g_hA1[2 * 4 * 16 * 2560];
__device__ __half g_Bp0[16 * 18 * 5120];        // [strip][kt32] B-blocks
__device__ __half g_Bp1[16 * 32 * 5120];
__device__ float g_bias0[16 * 128];
__device__ float g_bias1[16 * 128];
__device__ float g_part[64 * 8192];             // per-tile fp32 gate partials
__device__ unsigned g_pflag[64];
__device__ float g_h1x[256 * 512];
__device__ unsigned g_cnt[4 * 32];              // per-mt group barrier
__device__ unsigned g_phs[4 * 32];

// ---------------- helpers ----------------------------------------------------
__device__ __forceinline__ uint32_t smem_u32(const void* p) {
    uint32_t a;
    asm("{ .reg .u64 t; cvta.to.shared.u64 t, %1; cvt.u32.u64 %0, t; }" : "=r"(a) : "l"(p));
    return a;
}
__device__ __forceinline__ unsigned ld_acq(const unsigned* p) {
    unsigned v;
    asm volatile("ld.acquire.gpu.global.b32 %0, [%1];" : "=r"(v) : "l"(p) : "memory");
    return v;
}
__device__ __forceinline__ unsigned atom_add_acqrel(unsigned* p, unsigned v) {
    unsigned o;
    asm volatile("atom.add.acq_rel.gpu.global.u32 %0, [%1], %2;" : "=r"(o) : "l"(p), "r"(v) : "memory");
    return o;
}
__device__ __forceinline__ void st_rel(unsigned* p, unsigned v) {
    asm volatile("st.release.gpu.global.b32 [%0], %1;" :: "l"(p), "r"(v) : "memory");
}
#define BARC() asm volatile("bar.sync 1, 256;" ::: "memory")   // compute warps only
#define MBAR_INIT(a, n) \
    asm volatile("mbarrier.init.shared.b64 [%0], %1;" :: "r"(a), "r"((uint32_t)(n)) : "memory")
#define MBAR_EXPECT_TX(a, b) \
    asm volatile("mbarrier.arrive.expect_tx.shared.b64 _, [%0], %1;" :: "r"(a), "r"((uint32_t)(b)) : "memory")
#define MBAR_ARRIVE(a) \
    asm volatile("mbarrier.arrive.shared.b64 _, [%0];" :: "r"(a) : "memory")
#define MBAR_WAIT(a, p) do {                                                               \
    asm volatile("{\n\t.reg .pred P1;\n\t"                                                 \
        "WL_%=:\n\t"                                                                       \
        "mbarrier.try_wait.parity.acquire.cta.shared::cta.b64 P1, [%0], %1, 0x989680;\n\t" \
        "@P1 bra.uni WD_%=;\n\t"                                                           \
        "bra.uni WL_%=;\n\t"                                                               \
        "WD_%=:\n\t}"                                                                      \
        :: "r"(a), "r"((uint32_t)(p)) : "memory");                                         \
} while (0)
#define BULK_G2S(dst, src, bytes, mbar)                                                    \
    asm volatile("cp.async.bulk.shared::cluster.global.mbarrier::complete_tx::bytes "      \
                 "[%0], [%1], %2, [%3];"                                                   \
        :: "r"(dst), "l"(src), "r"((uint32_t)(bytes)), "r"(mbar) : "memory")

__device__ __forceinline__ void mma16(float* c, const uint32_t* a, uint32_t b0, uint32_t b1) {
    asm volatile(
        "mma.sync.aligned.m16n8k16.row.col.f32.f16.f16.f32 "
        "{%0,%1,%2,%3},{%4,%5,%6,%7},{%8,%9},{%0,%1,%2,%3};"
        : "+f"(c[0]), "+f"(c[1]), "+f"(c[2]), "+f"(c[3])
        : "r"(a[0]), "r"(a[1]), "r"(a[2]), "r"(a[3]), "r"(b0), "r"(b1));
}
__device__ __forceinline__ float hw_tanh(float x) {
    float y; asm("tanh.approx.f32 %0, %1;" : "=f"(y) : "f"(x));
    return y;
}
__device__ __forceinline__ float fsig(float x) { return fmaf(hw_tanh(0.5f * x), 0.5f, 0.5f); }
__device__ __forceinline__ uint32_t pk2(float a, float b) {
    __half2 h = __floats2half2_rn(a, b);
    return *(uint32_t*)&h;
}

// ---------------- prep kernels ------------------------------------------------
__global__ void prep_x(const float* __restrict__ x) {
    int idx = blockIdx.x * blockDim.x + threadIdx.x;
    if (idx >= 256 * 4 * 2 * 64 * 32) return;
    int kk = idx & 31;
    int r  = (idx >> 5) & 63;
    int kc = (idx >> 11) & 1;
    int mt = (idx >> 12) & 3;
    int t  = idx >> 14;
    int b = mt * 64 + r, d = kc * 32 + kk;
    g_xA[(size_t)((t * 4 + mt) * 2 + kc) * 2560 + r * 40 + kk] =
        __float2half(x[(b * 256 + t) * 64 + d]);
}
__global__ void prep_w(const float* __restrict__ Wih0, const float* __restrict__ Whh0,
                       const float* __restrict__ bih0, const float* __restrict__ bhh0,
                       const float* __restrict__ Wih1, const float* __restrict__ Whh1,
                       const float* __restrict__ bih1, const float* __restrict__ bhh1) {
    int idx = blockIdx.x * blockDim.x + threadIdx.x;
    const int NW0 = 16 * 18 * 128 * 32;
    const int NW1 = 16 * 32 * 128 * 32;
    if (idx < NW0) {
        int kk = idx & 31;
        int n  = (idx >> 5) & 127;
        int kt = (idx >> 12) % 18;
        int nt = idx / (18 * 4096);
        int row = (n & 3) * 512 + nt * 32 + (n >> 2);
        int k = kt * 32 + kk;
        float v = (k < 64) ? Wih0[row * 64 + k] : Whh0[row * 512 + (k - 64)];
        g_Bp0[(size_t)(nt * 18 + kt) * 5120 + n * 40 + kk] = __float2half(v);
    } else if (idx < NW0 + NW1) {
        int j = idx - NW0;
        int kk = j & 31;
        int n  = (j >> 5) & 127;
        int kt = (j >> 12) & 31;
        int nt = j >> 17;
        int row = (n & 3) * 512 + nt * 32 + (n >> 2);
        int k = kt * 32 + kk;
        float v = (k < 512) ? Wih1[row * 512 + k] : Whh1[row * 512 + (k - 512)];
        g_Bp1[(size_t)(nt * 32 + kt) * 5120 + n * 40 + kk] = __float2half(v);
    } else if (idx < NW0 + NW1 + 2 * 2048) {
        int j = idx - NW0 - NW1;
        int l = j >> 11;
        int rr = j & 2047;
        int c = rr & 127, nt = rr >> 7;
        int row = (c & 3) * 512 + nt * 32 + (c >> 2);
        float v = l ? (bih1[row] + bhh1[row]) : (bih0[row] + bhh0[row]);
        (l ? g_bias1 : g_bias0)[rr] = v;
    }
}
__global__ void prep_zero() {
    int idx = blockIdx.x * blockDim.x + threadIdx.x;
    if (idx < 2 * 4 * 16 * 2560) {
        g_hA0[idx] = __float2half(0.f);
        g_hA1[idx] = __float2half(0.f);
    }
    if (idx < 64) g_pflag[idx] = 0u;
    if (idx < 128) { g_cnt[idx] = 0u; g_phs[idx] = 0u; }
}

// ---------------- persistent LSTM kernel ---------------------------------------
__global__ __launch_bounds__(THREADS, 1)
void lstm_persistent(const float* __restrict__ Wfc, const float* __restrict__ bfc,
                     float* __restrict__ out) {
    extern __shared__ char dsm_raw[];
    __shared__ __align__(8) unsigned long long mb_full[STAGES], mb_empty[STAGES];
    __shared__ float Gs[64 * 132];
    __shared__ float bias_s[128];
    __shared__ float red[NCW];

    const int tid   = threadIdx.x;
    const int lane  = tid & 31;
    const int warp  = tid >> 5;
    const int warpM = warp >> 2;   // 0..1 (compute warps only)
    const int warpN = warp & 3;
    const int bid   = blockIdx.x;
    const int layer = bid >> 6;
    const int tile  = bid & 63;
    const int mt    = tile & 3;
    const int strip = tile >> 2;
    const bool is_comp = (tid < NCW);
    const bool is_prod = (tid == NCW);   // single producer thread (warp 8 lane 0)

    uint32_t rawu  = smem_u32(dsm_raw);
    uint32_t dsm_u = (rawu + 127u) & ~127u;
    char* sbase = dsm_raw + (dsm_u - rawu);
    uint32_t fullA[STAGES], emptyA[STAGES], aSt[STAGES];
#pragma unroll
    for (int s = 0; s < STAGES; s++) {
        aSt[s] = dsm_u + s * STAGE_BYTES;
        fullA[s]  = smem_u32(&mb_full[s]);
        emptyA[s] = smem_u32(&mb_empty[s]);
    }
    if (tid == 0) {
#pragma unroll
        for (int s = 0; s < STAGES; s++) { MBAR_INIT(fullA[s], 1); MBAR_INIT(emptyA[s], 8); }
    }
    for (int i = tid; i < 128; i += THREADS)
        bias_s[i] = ((layer ? g_bias1 : g_bias0) + strip * 128)[i];
    __syncthreads();

    float cst[8];
#pragma unroll
    for (int j = 0; j < 8; j++) cst[j] = 0.f;
    float acc[2][4][4];

    int p_st = 0, p_ph = 1;   // producer cursor
    int c_st = 0, c_ph = 0;   // consumer cursor
    unsigned target = 0;

    for (int s = 0; s <= 256; s++) {
        const int rp = (s + 1) & 1;
        const int pidx = (layer == 0 && s >= 1) ? 2 : 0;   // partner chunks (K128)
        int nch;
        if (layer == 0) nch = pidx + (s < 256 ? 5 : 0);    // own: 1x K64 + 4x K128
        else            nch = (s >= 1) ? 6 : 0;            // 6x K128

        if (nch > 0) {
            if (is_prod) {
                // -------- producer: variable-size chunks, throttled by empty stages
                for (int c = 0; c < nch; c++) {
                    const __half* a;
                    const __half* b;
                    int nsub;
                    if (layer == 0) {
                        if (c < pidx) {                    // partner: h1 cols 256..511
                            a = g_hA1 + (size_t)((rp * 4 + mt) * 16 + 8 + 4 * c) * 2560;
                            b = g_Bp1 + (size_t)(strip * 32 + 24 + 4 * c) * 5120;
                            nsub = 4;
                        } else {
                            int j = c - pidx;
                            if (j == 0) {                  // x chunk (K64)
                                a = g_xA + (size_t)((s * 4 + mt) * 2) * 2560;
                                b = g_Bp0 + (size_t)(strip * 18) * 5120;
                                nsub = 2;
                            } else {                       // h0 chunks (K128)
                                a = g_hA0 + (size_t)((rp * 4 + mt) * 16 + 4 * (j - 1)) * 2560;
                                b = g_Bp0 + (size_t)(strip * 18 + 2 + 4 * (j - 1)) * 5120;
                                nsub = 4;
                            }
                        }
                    } else {
                        if (c < 4) {                       // h0 K 0..511
                            a = g_hA0 + (size_t)((rp * 4 + mt) * 16 + 4 * c) * 2560;
                            b = g_Bp1 + (size_t)(strip * 32 + 4 * c) * 5120;
                        } else {                           // h1 cols 0..255
                            a = g_hA1 + (size_t)((rp * 4 + mt) * 16 + 4 * (c - 4)) * 2560;
                            b = g_Bp1 + (size_t)(strip * 32 + 16 + 4 * (c - 4)) * 5120;
                        }
                        nsub = 4;
                    }
                    MBAR_WAIT(emptyA[p_st], p_ph);
                    MBAR_EXPECT_TX(fullA[p_st], (uint32_t)(nsub * 15360));
                    BULK_G2S(aSt[p_st], a, (uint32_t)(nsub * 5120), fullA[p_st]);
                    BULK_G2S(aSt[p_st] + A_MAX, b, (uint32_t)(nsub * 10240), fullA[p_st]);
                    if (++p_st == STAGES) { p_st = 0; p_ph ^= 1; }
                }
            } else if (is_comp) {
                // -------- compute warps
#pragma unroll
                for (int mi = 0; mi < 2; mi++)
#pragma unroll
                    for (int ni = 0; ni < 4; ni++)
#pragma unroll
                        for (int q = 0; q < 4; q++) acc[mi][ni][q] = 0.f;

                for (int c = 0; c < nch; c++) {
                    int nsub = 4;
                    if (layer == 0 && c == pidx) nsub = 2;   // x chunk

                    int st = c_st;
                    MBAR_WAIT(fullA[st], c_ph);
                    if (++c_st == STAGES) { c_st = 0; c_ph ^= 1; }

                    const uint32_t* stW = (const uint32_t*)(sbase + st * STAGE_BYTES);
                    for (int sub = 0; sub < nsub; sub++) {
                        const uint32_t* aw = stW + sub * 1280;
                        const uint32_t* bw = stW + 5120 + sub * 2560;
#pragma unroll
                        for (int kk = 0; kk < 2; kk++) {
                            uint32_t af[2][4], bf[4][2];
#pragma unroll
                            for (int mi = 0; mi < 2; mi++) {
                                int rb = warpM * 32 + mi * 16 + (lane >> 2);
                                int wi = rb * 20 + (lane & 3) + kk * 8;
                                af[mi][0] = aw[wi];
                                af[mi][1] = aw[wi + 160];
                                af[mi][2] = aw[wi + 4];
                                af[mi][3] = aw[wi + 164];
                            }
#pragma unroll
                            for (int ni = 0; ni < 4; ni++) {
                                int nb = warpN * 32 + ni * 8 + (lane >> 2);
                                int wi = nb * 20 + (lane & 3) + kk * 8;
                                bf[ni][0] = bw[wi];
                                bf[ni][1] = bw[wi + 4];
                            }
#pragma unroll
                            for (int mi = 0; mi < 2; mi++)
#pragma unroll
                                for (int ni = 0; ni < 4; ni++)
                                    mma16(acc[mi][ni], af[mi], bf[ni][0], bf[ni][1]);
                        }
                    }
                    if (lane == 0) MBAR_ARRIVE(emptyA[st]);

                    if (layer == 0 && pidx && c == pidx - 1) {
                        float2* pp = (float2*)&g_part[(size_t)tile * 8192];
#pragma unroll
                        for (int mi = 0; mi < 2; mi++) {
                            int rr = warpM * 32 + mi * 16 + (lane >> 2);
#pragma unroll
                            for (int ni = 0; ni < 4; ni++) {
                                int cc = warpN * 32 + ni * 8 + (lane & 3) * 2;
                                pp[(rr * 128 + cc) >> 1]       = make_float2(acc[mi][ni][0], acc[mi][ni][1]);
                                pp[((rr + 8) * 128 + cc) >> 1] = make_float2(acc[mi][ni][2], acc[mi][ni][3]);
                            }
                        }
                        BARC();
                        if (tid == 0) st_rel(&g_pflag[tile], (unsigned)s);
#pragma unroll
                        for (int mi = 0; mi < 2; mi++)
#pragma unroll
                            for (int ni = 0; ni < 4; ni++)
#pragma unroll
                                for (int q = 0; q < 4; q++) acc[mi][ni][q] = 0.f;
                    }
                    if (layer == 1 && c == 4 && tid == 0) {
                        while (ld_acq(&g_pflag[tile]) < (unsigned)s) { }
                    }
                }

                // -------- epilogue (compute warps only)
                bool do_epi = (layer == 1) || (s < 256);
                if (do_epi) {
#pragma unroll
                    for (int mi = 0; mi < 2; mi++) {
                        int rr = warpM * 32 + mi * 16 + (lane >> 2);
#pragma unroll
                        for (int ni = 0; ni < 4; ni++) {
                            int cc = warpN * 32 + ni * 8 + (lane & 3) * 2;
                            Gs[rr * 132 + cc]           = acc[mi][ni][0];
                            Gs[rr * 132 + cc + 1]       = acc[mi][ni][1];
                            Gs[(rr + 8) * 132 + cc]     = acc[mi][ni][2];
                            Gs[(rr + 8) * 132 + cc + 1] = acc[mi][ni][3];
                        }
                    }
                    BARC();

                    int r   = tid >> 2;
                    int hl0 = (tid & 3) * 8;
                    float hv[8];
                    if (layer == 0) {
#pragma unroll
                        for (int j = 0; j < 8; j++) {
                            int c4 = (hl0 + j) * 4;
                            float ip = Gs[r * 132 + c4 + 0] + bias_s[c4 + 0];
                            float fp = Gs[r * 132 + c4 + 1] + bias_s[c4 + 1];
                            float gp = Gs[r * 132 + c4 + 2] + bias_s[c4 + 2];
                            float op = Gs[r * 132 + c4 + 3] + bias_s[c4 + 3];
                            float cn = fsig(fp) * cst[j] + fsig(ip) * hw_tanh(gp);
                            cst[j] = cn;
                            hv[j] = fsig(op) * hw_tanh(cn);
                        }
                        __half* hout = g_hA0 + (size_t)(((s & 1) * 4 + mt) * 16 + strip) * 2560;
                        uint4 v = { pk2(hv[0], hv[1]), pk2(hv[2], hv[3]),
                                    pk2(hv[4], hv[5]), pk2(hv[6], hv[7]) };
                        *(uint4*)(&hout[r * 40 + hl0]) = v;
                    } else {
                        const float4* pin =
                            (const float4*)&g_part[(size_t)tile * 8192 + r * 128 + (tid & 3) * 32];
#pragma unroll
                        for (int j = 0; j < 8; j++) {
                            int c4 = (hl0 + j) * 4;
                            float4 pv = __ldcg(&pin[j]);
                            float ip = Gs[r * 132 + c4 + 0] + bias_s[c4 + 0] + pv.x;
                            float fp = Gs[r * 132 + c4 + 1] + bias_s[c4 + 1] + pv.y;
                            float gp = Gs[r * 132 + c4 + 2] + bias_s[c4 + 2] + pv.z;
                            float op = Gs[r * 132 + c4 + 3] + bias_s[c4 + 3] + pv.w;
                            float cn = fsig(fp) * cst[j] + fsig(ip) * hw_tanh(gp);
                            cst[j] = cn;
                            hv[j] = fsig(op) * hw_tanh(cn);
                        }
                        __half* hout = g_hA1 + (size_t)(((s & 1) * 4 + mt) * 16 + strip) * 2560;
                        uint4 v = { pk2(hv[0], hv[1]), pk2(hv[2], hv[3]),
                                    pk2(hv[4], hv[5]), pk2(hv[6], hv[7]) };
                        *(uint4*)(&hout[r * 40 + hl0]) = v;
                        if (s == 256) {
#pragma unroll
                            for (int j = 0; j < 8; j++)
                                g_h1x[(mt * 64 + r) * 512 + strip * 32 + hl0 + j] = hv[j];
                        }
                    }
                }
            }
        }

        // -------- per-mt group barrier (32 CTAs; all 288 threads sync) --------
        target++;
        __syncthreads();
        if (tid == 0) {
            __threadfence();
            unsigned a = atom_add_acqrel(&g_cnt[mt << 5], 1u) + 1u;
            if (a == target * 32u) st_rel(&g_phs[mt << 5], target);
            else while (ld_acq(&g_phs[mt << 5]) < target) { }
        }
        __syncthreads();
    }

    // -------- final FC (compute warps only) --------
    if (is_comp) {
        int gidx = layer ? (16 + strip) : strip;
        for (int r2 = 0; r2 < 2; r2++) {
            int b = mt * 64 + 2 * gidx + r2;
            float p = 0.f;
            for (int k = tid; k < 512; k += NCW)
                p += __ldcg(&g_h1x[b * 512 + k]) * __ldg(&Wfc[k]);
            red[tid] = p;
            BARC();
            for (int off = 128; off > 0; off >>= 1) {
                if (tid < off) red[tid] += red[tid + off];
                BARC();
            }
            if (tid == 0) out[b] = red[0] + __ldg(bfc);
            BARC();
        }
    }
}

// ---------------- launch --------------------------------------------------------
extern "C" void kernel_launch(void* const* d_in, const int* in_sizes, int n_in,
                              void* d_out, int out_size) {
    const float* x    = (const float*)d_in[0];
    const float* Wih0 = (const float*)d_in[1];
    const float* Whh0 = (const float*)d_in[2];
    const float* bih0 = (const float*)d_in[3];
    const float* bhh0 = (const float*)d_in[4];
    const float* Wih1 = (const float*)d_in[5];
    const float* Whh1 = (const float*)d_in[6];
    const float* bih1 = (const float*)d_in[7];
    const float* bhh1 = (const float*)d_in[8];
    const float* Wfc  = (const float*)d_in[9];
    const float* bfc  = (const float*)d_in[10];
    float* out = (float*)d_out;

    cudaFuncSetAttribute(lstm_persistent,
                         cudaFuncAttributeMaxDynamicSharedMemorySize,
                         STAGES * STAGE_BYTES + 256);

    prep_x<<<(256 * 4 * 2 * 64 * 32 + 255) / 256, 256>>>(x);
    int wtot = 16 * 18 * 128 * 32 + 16 * 32 * 128 * 32 + 2 * 2048;
    prep_w<<<(wtot + 255) / 256, 256>>>(Wih0, Whh0, bih0, bhh0, Wih1, Whh1, bih1, bhh1);
    prep_zero<<<(2 * 4 * 16 * 2560 + 255) / 256, 256>>>();
    lstm_persistent<<<NBLK, THREADS, STAGES * STAGE_BYTES + 256>>>(Wfc, bfc, out);
}